// round 12
// baseline (speedup 1.0000x reference)
#include <cuda_runtime.h>

// Sinkhorn OT loss on 64x64 pooled grids. K = exp(-C/0.1) is exact (to fp32)
// as two 3-tap separable passes, W1 = exp(-10).
// R12: R10's zero-communication domain overlap (8 row-blocks/batch, 16-row
// window = 8 owned + 4+4 halo), but each CTA now carries TWO batches with all
// state duplicated per thread. The second batch is independent in-thread ILP:
// it fills the ~230 cyc of exposed SHFL/STS/BAR/LDS/RCP latency that R10's
// single warp per SMSP could not hide. One __syncthreads serves both batches.
// Grid = 64 CTAs (8 batch-pairs x 8 row-blocks) x 128 threads.

#define NBATCH 16
#define ITERS  50
#define EPS    1e-8f
#define W1     4.5399929762484854e-05f   // exp(-10)

__device__ float g_pooled[2][NBATCH][4096];
__device__ float g_psum[2][NBATCH][16];    // per pool-block partial sums
__device__ float g_costs[NBATCH * 8];      // [batch*8 + block]
__device__ int   g_done;

// ---------------------------------------------------------------- pooling
__global__ __launch_bounds__(256) void pool_kernel(const float* __restrict__ pred,
                                                   const float* __restrict__ gt) {
    __shared__ float red[8];
    const int bid    = blockIdx.x;          // 0..511
    const int tensor = bid >> 8;
    const int batch  = (bid >> 4) & 15;
    const int rb     = bid & 15;            // block of 4 pooled rows
    const float* src = (tensor ? gt : pred) + (size_t)batch * 262144;

    const int pr = rb * 4 + (threadIdx.x >> 6);
    const int pc = threadIdx.x & 63;
    const float4* p = (const float4*)(src + (size_t)pr * 4096 + pc * 8);

    float s = 0.f;
#pragma unroll
    for (int y = 0; y < 8; ++y) {
        float4 v0 = p[y * 128];
        float4 v1 = p[y * 128 + 1];
        s += (v0.x + v0.y) + (v0.z + v0.w) + (v1.x + v1.y) + (v1.z + v1.w);
    }
    g_pooled[tensor][batch][pr * 64 + pc] = s;

    float v = s;
#pragma unroll
    for (int o = 16; o; o >>= 1) v += __shfl_xor_sync(0xffffffffu, v, o);
    const int w = threadIdx.x >> 5, l = threadIdx.x & 31;
    if (l == 0) red[w] = v;
    __syncthreads();
    if (threadIdx.x == 0) {
        float tot = ((red[0] + red[1]) + (red[2] + red[3]))
                  + ((red[4] + red[5]) + (red[6] + red[7]));
        g_psum[tensor][batch][rb] = tot;
    }
}

// ---------------------------------------------------------------- sinkhorn
__global__ __launch_bounds__(128, 1) void sinkhorn_kernel(float* __restrict__ out) {
    // [batch-in-pair][slot][band+1][col]; band rows 0 & 9 stay 0 = window pads
    __shared__ __align__(16) float HT[2][2][10][64];
    __shared__ __align__(16) float HB[2][2][10][64];
    __shared__ float red[2][4];

    const int t     = threadIdx.x;
    const int w     = t >> 5, l = t & 31;
    const int seg   = l & 15;
    const int band  = 2 * w + (l >> 4);    // 0..7, 2 window-rows each
    const int c0    = seg * 4;
    const int q     = blockIdx.x & 7;      // row-block (8 rows) within batch
    const int pair  = blockIdx.x >> 3;     // batch pair: batches 2*pair, 2*pair+1
    const int r0    = 8 * q - 4 + 2 * band;   // window rows 8q-4 .. 8q+11
    const bool own  = (band >= 2) && (band < 6);

    // zero smem (pads included)
    for (int i = t; i < 2 * 2 * 10 * 64; i += 128) {
        ((float*)HT)[i] = 0.f;
        ((float*)HB)[i] = 0.f;
    }

    // ---- per-batch sums, loads, normalize ----
    float a[2][2][4], b[2][2][4], u[2][2][4], v[2][2][4];
#pragma unroll
    for (int p = 0; p < 2; ++p) {
        const int batch = 2 * pair + p;
        float asum = 0.f, bsum = 0.f;
#pragma unroll
        for (int i = 0; i < 16; ++i) {
            asum += g_psum[0][batch][i];
            bsum += g_psum[1][batch][i];
        }
        const float ra  = 1.f / fmaxf(asum, 1e-8f);
        const float rbv = 1.f / fmaxf(bsum, 1e-8f);
#pragma unroll
        for (int i = 0; i < 2; ++i) {
            const int r = r0 + i;
            if ((unsigned)r < 64u) {
                const float4 x = *(const float4*)&g_pooled[0][batch][r * 64 + c0];
                const float4 y = *(const float4*)&g_pooled[1][batch][r * 64 + c0];
                a[p][i][0] = x.x * ra;  a[p][i][1] = x.y * ra;
                a[p][i][2] = x.z * ra;  a[p][i][3] = x.w * ra;
                b[p][i][0] = y.x * rbv; b[p][i][1] = y.y * rbv;
                b[p][i][2] = y.z * rbv; b[p][i][3] = y.w * rbv;
#pragma unroll
                for (int j = 0; j < 4; ++j) u[p][i][j] = 1.f;
            } else {
#pragma unroll
                for (int j = 0; j < 4; ++j) {
                    a[p][i][j] = 0.f; b[p][i][j] = 0.f; u[p][i][j] = 0.f;
                }
            }
        }
    }
    __syncthreads();   // smem zeroing visible

    // out = tg / (Ve(He(in)) + eps) for BOTH batches; one barrier per halfstep
    auto halfstep = [&](float (&o)[2][2][4], const float (&tg)[2][2][4],
                        const float (&in)[2][2][4], const int s) {
        float H[2][2][4];
#pragma unroll
        for (int p = 0; p < 2; ++p) {
#pragma unroll
            for (int i = 0; i < 2; ++i) {
                float lf = __shfl_up_sync(0xffffffffu, in[p][i][3], 1, 16);
                float rt = __shfl_down_sync(0xffffffffu, in[p][i][0], 1, 16);
                if (seg == 0)  lf = 0.f;
                if (seg == 15) rt = 0.f;
                H[p][i][0] = fmaf(W1, lf + in[p][i][1],         in[p][i][0]);
                H[p][i][1] = fmaf(W1, in[p][i][0] + in[p][i][2], in[p][i][1]);
                H[p][i][2] = fmaf(W1, in[p][i][1] + in[p][i][3], in[p][i][2]);
                H[p][i][3] = fmaf(W1, in[p][i][2] + rt,          in[p][i][3]);
            }
            *(float4*)&HT[p][s][band + 1][c0] =
                make_float4(H[p][0][0], H[p][0][1], H[p][0][2], H[p][0][3]);
            *(float4*)&HB[p][s][band + 1][c0] =
                make_float4(H[p][1][0], H[p][1][1], H[p][1][2], H[p][1][3]);
        }
        __syncthreads();
#pragma unroll
        for (int p = 0; p < 2; ++p) {
            const float4 u4 = *(const float4*)&HB[p][s][band][c0];      // row r0-1
            const float4 d4 = *(const float4*)&HT[p][s][band + 2][c0];  // row r0+2
            const float up[4] = {u4.x, u4.y, u4.z, u4.w};
            const float dn[4] = {d4.x, d4.y, d4.z, d4.w};
#pragma unroll
            for (int j = 0; j < 4; ++j) {
                const float d0 = fmaf(W1, up[j] + H[p][1][j], H[p][0][j] + EPS);
                const float d1 = fmaf(W1, H[p][0][j] + dn[j], H[p][1][j] + EPS);
                o[p][0][j] = __fdividef(tg[p][0][j], d0);
                o[p][1][j] = __fdividef(tg[p][1][j], d1);
            }
        }
    };

#pragma unroll 1
    for (int it = 0; it < ITERS; ++it) {
        halfstep(v, b, u, 0);
        halfstep(u, a, v, 1);
    }

    // ---- per-batch cost over owned rows: u.(Mv),
    //      Mv = Hg(v) + W1*(T[r-1]+T[r+1]), T = v + 2*Hg(v) ----
    float local[2];
#pragma unroll
    for (int p = 0; p < 2; ++p) {
        float HG[2][4], T[2][4];
#pragma unroll
        for (int i = 0; i < 2; ++i) {
            float lf = __shfl_up_sync(0xffffffffu, v[p][i][3], 1, 16);
            float rt = __shfl_down_sync(0xffffffffu, v[p][i][0], 1, 16);
            if (seg == 0)  lf = 0.f;
            if (seg == 15) rt = 0.f;
            HG[i][0] = W1 * (lf + v[p][i][1]);
            HG[i][1] = W1 * (v[p][i][0] + v[p][i][2]);
            HG[i][2] = W1 * (v[p][i][1] + v[p][i][3]);
            HG[i][3] = W1 * (v[p][i][2] + rt);
#pragma unroll
            for (int j = 0; j < 4; ++j) T[i][j] = fmaf(2.f, HG[i][j], v[p][i][j]);
        }
        // slot 0 reuse safe: last readers synced inside final s=1 halfstep
        *(float4*)&HT[p][0][band + 1][c0] = make_float4(T[0][0], T[0][1], T[0][2], T[0][3]);
        *(float4*)&HB[p][0][band + 1][c0] = make_float4(T[1][0], T[1][1], T[1][2], T[1][3]);
        __syncthreads();
        const float4 u4 = *(const float4*)&HB[p][0][band][c0];
        const float4 d4 = *(const float4*)&HT[p][0][band + 2][c0];
        const float up[4] = {u4.x, u4.y, u4.z, u4.w};
        const float dn[4] = {d4.x, d4.y, d4.z, d4.w};

        float lc = 0.f;
#pragma unroll
        for (int j = 0; j < 4; ++j) {
            const float mv0 = fmaf(W1, up[j] + T[1][j], HG[0][j]);
            const float mv1 = fmaf(W1, T[0][j] + dn[j], HG[1][j]);
            lc = fmaf(u[p][0][j], mv0, fmaf(u[p][1][j], mv1, lc));
        }
        local[p] = own ? lc : 0.f;
    }

    // block reduce both
#pragma unroll
    for (int p = 0; p < 2; ++p) {
#pragma unroll
        for (int o = 16; o; o >>= 1)
            local[p] += __shfl_xor_sync(0xffffffffu, local[p], o);
        if (l == 0) red[p][w] = local[p];
    }
    __syncthreads();

    if (t == 0) {
        g_costs[(2 * pair)     * 8 + q] = (red[0][0] + red[0][1]) + (red[0][2] + red[0][3]);
        g_costs[(2 * pair + 1) * 8 + q] = (red[1][0] + red[1][1]) + (red[1][2] + red[1][3]);
        __threadfence();
        const int prev = atomicAdd(&g_done, 1);
        if (prev == 64 - 1) {
            g_done = 0;
            __threadfence();
            float s = 0.f;
#pragma unroll 1
            for (int bb = 0; bb < NBATCH; ++bb) {
                float as = 0.f, bs = 0.f;
#pragma unroll
                for (int i = 0; i < 16; ++i) {
                    as += g_psum[0][bb][i];
                    bs += g_psum[1][bb][i];
                }
                float cst = 0.f;
#pragma unroll
                for (int k = 0; k < 8; ++k) cst += g_costs[8 * bb + k];
                s += ((as > 0.5f) && (bs > 0.5f)) ? cst : 0.f;
            }
            out[0] = s * (1.f / (float)NBATCH);
        }
    }
}

extern "C" void kernel_launch(void* const* d_in, const int* in_sizes, int n_in,
                              void* d_out, int out_size) {
    (void)in_sizes; (void)n_in; (void)out_size;
    const float* pred = (const float*)d_in[0];
    const float* gt   = (const float*)d_in[1];
    pool_kernel<<<512, 256>>>(pred, gt);
    sinkhorn_kernel<<<64, 128>>>((float*)d_out);
}

// round 13
// speedup vs baseline: 1.0547x; 1.0547x over previous
#include <cuda_runtime.h>

// Sinkhorn OT loss on 64x64 pooled grids. K = exp(-C/0.1) is exact (to fp32)
// as two 3-tap separable passes, W1 = exp(-10).
// R13: zero-communication domain overlap with CO-RESIDENT CTAs. 16 row-blocks
// per batch (4 owned rows, 12-row window = 4+4 halo; same halo depth and
// accuracy as R10). CTA = 96 threads / 3 warps, grid = 256 -> ~2 independent
// CTAs per SM. R12 showed in-thread batch pairing serializes behind the same
// barrier; co-resident CTAs have INDEPENDENT barriers, so one CTA's BAR/LDS/
// SHFL stalls are filled by the other's issue -- hardware interleaving.

#define NBATCH 16
#define ITERS  50
#define EPS    1e-8f
#define W1     4.5399929762484854e-05f   // exp(-10)

__device__ float g_pooled[2][NBATCH][4096];
__device__ float g_psum[2][NBATCH][16];    // per pool-block partial sums
__device__ float g_costs[NBATCH * 16];     // [batch*16 + block]
__device__ int   g_done;

// ---------------------------------------------------------------- pooling
__global__ __launch_bounds__(256) void pool_kernel(const float* __restrict__ pred,
                                                   const float* __restrict__ gt) {
    __shared__ float red[8];
    const int bid    = blockIdx.x;          // 0..511
    const int tensor = bid >> 8;
    const int batch  = (bid >> 4) & 15;
    const int rb     = bid & 15;            // block of 4 pooled rows
    const float* src = (tensor ? gt : pred) + (size_t)batch * 262144;

    const int pr = rb * 4 + (threadIdx.x >> 6);
    const int pc = threadIdx.x & 63;
    const float4* p = (const float4*)(src + (size_t)pr * 4096 + pc * 8);

    float s = 0.f;
#pragma unroll
    for (int y = 0; y < 8; ++y) {
        float4 v0 = p[y * 128];
        float4 v1 = p[y * 128 + 1];
        s += (v0.x + v0.y) + (v0.z + v0.w) + (v1.x + v1.y) + (v1.z + v1.w);
    }
    g_pooled[tensor][batch][pr * 64 + pc] = s;

    float v = s;
#pragma unroll
    for (int o = 16; o; o >>= 1) v += __shfl_xor_sync(0xffffffffu, v, o);
    const int w = threadIdx.x >> 5, l = threadIdx.x & 31;
    if (l == 0) red[w] = v;
    __syncthreads();
    if (threadIdx.x == 0) {
        float tot = ((red[0] + red[1]) + (red[2] + red[3]))
                  + ((red[4] + red[5]) + (red[6] + red[7]));
        g_psum[tensor][batch][rb] = tot;
    }
}

// ---------------------------------------------------------------- sinkhorn
__global__ __launch_bounds__(96) void sinkhorn_kernel(float* __restrict__ out) {
    // seam rows, double-buffered by slot; index band+1; rows 0 & 7 = 0 pads
    __shared__ __align__(16) float HT[2][8][64];   // each band's H row 2b   (upper)
    __shared__ __align__(16) float HB[2][8][64];   // each band's H row 2b+1 (lower)
    __shared__ float red[3];

    const int t     = threadIdx.x;
    const int w     = t >> 5, l = t & 31;
    const int seg   = l & 15;
    const int band  = 2 * w + (l >> 4);    // 0..5, 2 window-rows each
    const int c0    = seg * 4;
    const int q     = blockIdx.x & 15;     // row-block (4 owned rows)
    const int batch = blockIdx.x >> 4;
    const int r0    = 4 * q - 4 + 2 * band;   // window rows 4q-4 .. 4q+7
    const bool own  = (band == 2) || (band == 3);   // owned rows 4q..4q+3

    // zero pads (only rows 0 and 7 are never overwritten, but zero-all is cheap)
    for (int i = t; i < 2 * 8 * 64; i += 96) {
        ((float*)HT)[i] = 0.f;
        ((float*)HB)[i] = 0.f;
    }

    // ---- batch-wide sums from pool partials (fixed linear order) ----
    float asum = 0.f, bsum = 0.f;
#pragma unroll
    for (int i = 0; i < 16; ++i) {
        asum += g_psum[0][batch][i];
        bsum += g_psum[1][batch][i];
    }
    const float ra  = 1.f / fmaxf(asum, 1e-8f);
    const float rbv = 1.f / fmaxf(bsum, 1e-8f);

    // ---- load window rows (zero outside the 64-row grid) ----
    float a[2][4], b[2][4], u[2][4], v[2][4];
#pragma unroll
    for (int i = 0; i < 2; ++i) {
        const int r = r0 + i;
        if ((unsigned)r < 64u) {
            const float4 x = *(const float4*)&g_pooled[0][batch][r * 64 + c0];
            const float4 y = *(const float4*)&g_pooled[1][batch][r * 64 + c0];
            a[i][0] = x.x * ra;  a[i][1] = x.y * ra;
            a[i][2] = x.z * ra;  a[i][3] = x.w * ra;
            b[i][0] = y.x * rbv; b[i][1] = y.y * rbv;
            b[i][2] = y.z * rbv; b[i][3] = y.w * rbv;
#pragma unroll
            for (int j = 0; j < 4; ++j) u[i][j] = 1.f;
        } else {
#pragma unroll
            for (int j = 0; j < 4; ++j) { a[i][j] = 0.f; b[i][j] = 0.f; u[i][j] = 0.f; }
        }
    }
    __syncthreads();   // pad init visible

    // out = tg / (Ve(He(in)) + eps); one __syncthreads per halfstep
    auto halfstep = [&](float (&o)[2][4], const float (&tg)[2][4],
                        const float (&in)[2][4], const int s) {
        float H0[4], H1[4];
        {
            float lf0 = __shfl_up_sync(0xffffffffu, in[0][3], 1, 16);
            float rt0 = __shfl_down_sync(0xffffffffu, in[0][0], 1, 16);
            float lf1 = __shfl_up_sync(0xffffffffu, in[1][3], 1, 16);
            float rt1 = __shfl_down_sync(0xffffffffu, in[1][0], 1, 16);
            if (seg == 0)  { lf0 = 0.f; lf1 = 0.f; }
            if (seg == 15) { rt0 = 0.f; rt1 = 0.f; }
            H0[0] = fmaf(W1, lf0 + in[0][1],      in[0][0]);
            H0[1] = fmaf(W1, in[0][0] + in[0][2], in[0][1]);
            H0[2] = fmaf(W1, in[0][1] + in[0][3], in[0][2]);
            H0[3] = fmaf(W1, in[0][2] + rt0,      in[0][3]);
            H1[0] = fmaf(W1, lf1 + in[1][1],      in[1][0]);
            H1[1] = fmaf(W1, in[1][0] + in[1][2], in[1][1]);
            H1[2] = fmaf(W1, in[1][1] + in[1][3], in[1][2]);
            H1[3] = fmaf(W1, in[1][2] + rt1,      in[1][3]);
        }
        *(float4*)&HT[s][band + 1][c0] = make_float4(H0[0], H0[1], H0[2], H0[3]);
        *(float4*)&HB[s][band + 1][c0] = make_float4(H1[0], H1[1], H1[2], H1[3]);
        __syncthreads();
        const float4 u4 = *(const float4*)&HB[s][band][c0];      // H row r0-1
        const float4 d4 = *(const float4*)&HT[s][band + 2][c0];  // H row r0+2
        const float up[4] = {u4.x, u4.y, u4.z, u4.w};
        const float dn[4] = {d4.x, d4.y, d4.z, d4.w};
#pragma unroll
        for (int j = 0; j < 4; ++j) {
            const float d0 = fmaf(W1, up[j] + H1[j], H0[j] + EPS);
            const float d1 = fmaf(W1, H0[j] + dn[j], H1[j] + EPS);
            o[0][j] = __fdividef(tg[0][j], d0);
            o[1][j] = __fdividef(tg[1][j], d1);
        }
    };

    for (int it = 0; it < ITERS; ++it) {
        halfstep(v, b, u, 0);
        halfstep(u, a, v, 1);
    }

    // ---- cost over OWNED rows: u.(Mv); Mv = Hg(v) + W1*(T[r-1]+T[r+1]),
    //      T = v + 2*Hg(v) ----
    float HG[2][4], T[2][4];
    {
        float lf0 = __shfl_up_sync(0xffffffffu, v[0][3], 1, 16);
        float rt0 = __shfl_down_sync(0xffffffffu, v[0][0], 1, 16);
        float lf1 = __shfl_up_sync(0xffffffffu, v[1][3], 1, 16);
        float rt1 = __shfl_down_sync(0xffffffffu, v[1][0], 1, 16);
        if (seg == 0)  { lf0 = 0.f; lf1 = 0.f; }
        if (seg == 15) { rt0 = 0.f; rt1 = 0.f; }
        HG[0][0] = W1 * (lf0 + v[0][1]);     HG[1][0] = W1 * (lf1 + v[1][1]);
        HG[0][1] = W1 * (v[0][0] + v[0][2]); HG[1][1] = W1 * (v[1][0] + v[1][2]);
        HG[0][2] = W1 * (v[0][1] + v[0][3]); HG[1][2] = W1 * (v[1][1] + v[1][3]);
        HG[0][3] = W1 * (v[0][2] + rt0);     HG[1][3] = W1 * (v[1][2] + rt1);
#pragma unroll
        for (int i = 0; i < 2; ++i)
#pragma unroll
            for (int j = 0; j < 4; ++j) T[i][j] = fmaf(2.f, HG[i][j], v[i][j]);
    }
    // slot 0 reuse safe: its last readers synced inside the final s=1 halfstep
    *(float4*)&HT[0][band + 1][c0] = make_float4(T[0][0], T[0][1], T[0][2], T[0][3]);
    *(float4*)&HB[0][band + 1][c0] = make_float4(T[1][0], T[1][1], T[1][2], T[1][3]);
    __syncthreads();
    const float4 u4 = *(const float4*)&HB[0][band][c0];
    const float4 d4 = *(const float4*)&HT[0][band + 2][c0];
    const float up[4] = {u4.x, u4.y, u4.z, u4.w};
    const float dn[4] = {d4.x, d4.y, d4.z, d4.w};

    float local = 0.f;
#pragma unroll
    for (int j = 0; j < 4; ++j) {
        const float mv0 = fmaf(W1, up[j] + T[1][j], HG[0][j]);
        const float mv1 = fmaf(W1, T[0][j] + dn[j], HG[1][j]);
        local = fmaf(u[0][j], mv0, fmaf(u[1][j], mv1, local));
    }
    local = own ? local : 0.f;

    // block reduce over 3 warps
#pragma unroll
    for (int o = 16; o; o >>= 1) local += __shfl_xor_sync(0xffffffffu, local, o);
    if (l == 0) red[w] = local;
    __syncthreads();

    if (t == 0) {
        g_costs[blockIdx.x] = (red[0] + red[1]) + red[2];
        __threadfence();
        const int prev = atomicAdd(&g_done, 1);
        if (prev == 16 * NBATCH - 1) {
            g_done = 0;
            __threadfence();
            float s = 0.f;
#pragma unroll 1
            for (int bb = 0; bb < NBATCH; ++bb) {
                float as = 0.f, bs = 0.f;
#pragma unroll
                for (int i = 0; i < 16; ++i) {
                    as += g_psum[0][bb][i];
                    bs += g_psum[1][bb][i];
                }
                float cst = 0.f;
#pragma unroll
                for (int k = 0; k < 16; ++k) cst += g_costs[16 * bb + k];
                s += ((as > 0.5f) && (bs > 0.5f)) ? cst : 0.f;
            }
            out[0] = s * (1.f / (float)NBATCH);
        }
    }
}

extern "C" void kernel_launch(void* const* d_in, const int* in_sizes, int n_in,
                              void* d_out, int out_size) {
    (void)in_sizes; (void)n_in; (void)out_size;
    const float* pred = (const float*)d_in[0];
    const float* gt   = (const float*)d_in[1];
    pool_kernel<<<512, 256>>>(pred, gt);
    sinkhorn_kernel<<<NBATCH * 16, 96>>>((float*)d_out);
}

// round 14
// speedup vs baseline: 1.1963x; 1.1343x over previous
#include <cuda_runtime.h>

// Sinkhorn OT loss on 64x64 pooled grids. K = exp(-C/0.1) is exact (to fp32)
// as two 3-tap separable passes, W1 = exp(-10).
// R14: identical domain split to R10 (8 blocks/batch, 16-row window = 8 owned
// + 4+4 halo -> same arithmetic, same accuracy), but remapped to 4-ROW BANDS:
// CTA = 64 threads / 2 warps, thread = 4 rows x 4 cols. Rows 1,2 of each band
// are INTERIOR -- their entire V-phase (incl. divisions) executes BEFORE the
// barrier, so the post-BAR critical path holds only the two boundary rows
// (LDS -> FMA -> RCP -> MUL). BAR couples just 2 warps. R10's period was
// 130 issue + ~236 exposed chain; this fills the chain with interior work.

#define NBATCH 16
#define ITERS  50
#define EPS    1e-8f
#define W1     4.5399929762484854e-05f   // exp(-10)

__device__ float g_pooled[2][NBATCH][4096];
__device__ float g_psum[2][NBATCH][16];    // per pool-block partial sums
__device__ float g_costs[NBATCH * 8];      // [batch*8 + block]
__device__ int   g_done;

// ---------------------------------------------------------------- pooling
__global__ __launch_bounds__(256) void pool_kernel(const float* __restrict__ pred,
                                                   const float* __restrict__ gt) {
    __shared__ float red[8];
    const int bid    = blockIdx.x;          // 0..511
    const int tensor = bid >> 8;
    const int batch  = (bid >> 4) & 15;
    const int rb     = bid & 15;            // block of 4 pooled rows
    const float* src = (tensor ? gt : pred) + (size_t)batch * 262144;

    const int pr = rb * 4 + (threadIdx.x >> 6);
    const int pc = threadIdx.x & 63;
    const float4* p = (const float4*)(src + (size_t)pr * 4096 + pc * 8);

    float s = 0.f;
#pragma unroll
    for (int y = 0; y < 8; ++y) {
        float4 v0 = p[y * 128];
        float4 v1 = p[y * 128 + 1];
        s += (v0.x + v0.y) + (v0.z + v0.w) + (v1.x + v1.y) + (v1.z + v1.w);
    }
    g_pooled[tensor][batch][pr * 64 + pc] = s;

    float v = s;
#pragma unroll
    for (int o = 16; o; o >>= 1) v += __shfl_xor_sync(0xffffffffu, v, o);
    const int w = threadIdx.x >> 5, l = threadIdx.x & 31;
    if (l == 0) red[w] = v;
    __syncthreads();
    if (threadIdx.x == 0) {
        float tot = ((red[0] + red[1]) + (red[2] + red[3]))
                  + ((red[4] + red[5]) + (red[6] + red[7]));
        g_psum[tensor][batch][rb] = tot;
    }
}

// ---------------------------------------------------------------- sinkhorn
__global__ __launch_bounds__(64, 1) void sinkhorn_kernel(float* __restrict__ out) {
    // seam rows, double-buffered by slot; index band+1; rows 0 & 5 = 0 pads
    __shared__ __align__(16) float HT[2][6][64];   // each band's H row (top of band)
    __shared__ __align__(16) float HB[2][6][64];   // each band's H row (bottom of band)
    __shared__ float red[2];

    const int t     = threadIdx.x;          // 0..63
    const int band  = t >> 4;               // 0..3, 4 window-rows each
    const int seg   = t & 15;
    const int l     = t & 31;
    const int c0    = seg * 4;
    const int q     = blockIdx.x & 7;       // row-block within batch
    const int batch = blockIdx.x >> 3;
    const int r0    = 8 * q - 4 + 4 * band; // window rows 8q-4 .. 8q+11
    const bool own  = (band == 1) || (band == 2);   // owned rows 8q..8q+7

    // zero smem (incl. pad rows 0 and 5; stores only ever hit rows 1..4)
    for (int i = t; i < 2 * 6 * 64; i += 64) {
        ((float*)HT)[i] = 0.f;
        ((float*)HB)[i] = 0.f;
    }

    // ---- batch-wide sums from pool partials (fixed linear order) ----
    float asum = 0.f, bsum = 0.f;
#pragma unroll
    for (int i = 0; i < 16; ++i) {
        asum += g_psum[0][batch][i];
        bsum += g_psum[1][batch][i];
    }
    const float ra  = 1.f / fmaxf(asum, 1e-8f);
    const float rbv = 1.f / fmaxf(bsum, 1e-8f);

    // ---- load window rows (zero outside the 64-row grid) ----
    float a[4][4], b[4][4], u[4][4], v[4][4];
#pragma unroll
    for (int i = 0; i < 4; ++i) {
        const int r = r0 + i;
        if ((unsigned)r < 64u) {
            const float4 x = *(const float4*)&g_pooled[0][batch][r * 64 + c0];
            const float4 y = *(const float4*)&g_pooled[1][batch][r * 64 + c0];
            a[i][0] = x.x * ra;  a[i][1] = x.y * ra;
            a[i][2] = x.z * ra;  a[i][3] = x.w * ra;
            b[i][0] = y.x * rbv; b[i][1] = y.y * rbv;
            b[i][2] = y.z * rbv; b[i][3] = y.w * rbv;
#pragma unroll
            for (int j = 0; j < 4; ++j) u[i][j] = 1.f;
        } else {
#pragma unroll
            for (int j = 0; j < 4; ++j) { a[i][j] = 0.f; b[i][j] = 0.f; u[i][j] = 0.f; }
        }
    }
    __syncthreads();   // pad init visible

    // out = tg / (Ve(He(in)) + eps). Interior rows (1,2) fully computed BEFORE
    // the barrier; only boundary rows (0,3) wait on the seam exchange.
    auto halfstep = [&](float (&o)[4][4], const float (&tg)[4][4],
                        const float (&in)[4][4], const int s) {
        float H[4][4];
#pragma unroll
        for (int i = 0; i < 4; ++i) {
            float lf = __shfl_up_sync(0xffffffffu, in[i][3], 1, 16);
            float rt = __shfl_down_sync(0xffffffffu, in[i][0], 1, 16);
            if (seg == 0)  lf = 0.f;
            if (seg == 15) rt = 0.f;
            H[i][0] = fmaf(W1, lf + in[i][1],       in[i][0]);
            H[i][1] = fmaf(W1, in[i][0] + in[i][2], in[i][1]);
            H[i][2] = fmaf(W1, in[i][1] + in[i][3], in[i][2]);
            H[i][3] = fmaf(W1, in[i][2] + rt,       in[i][3]);
        }
        *(float4*)&HT[s][band + 1][c0] = make_float4(H[0][0], H[0][1], H[0][2], H[0][3]);
        *(float4*)&HB[s][band + 1][c0] = make_float4(H[3][0], H[3][1], H[3][2], H[3][3]);

        // interior rows 1,2: no seam dependence -> pre-BAR (fills the wait)
#pragma unroll
        for (int j = 0; j < 4; ++j) {
            const float d1 = fmaf(W1, H[0][j] + H[2][j], H[1][j] + EPS);
            const float d2 = fmaf(W1, H[1][j] + H[3][j], H[2][j] + EPS);
            o[1][j] = __fdividef(tg[1][j], d1);
            o[2][j] = __fdividef(tg[2][j], d2);
        }
        __syncthreads();
        const float4 u4 = *(const float4*)&HB[s][band][c0];      // H row r0-1
        const float4 d4 = *(const float4*)&HT[s][band + 2][c0];  // H row r0+4
        const float up[4] = {u4.x, u4.y, u4.z, u4.w};
        const float dn[4] = {d4.x, d4.y, d4.z, d4.w};
#pragma unroll
        for (int j = 0; j < 4; ++j) {
            const float d0 = fmaf(W1, up[j] + H[1][j], H[0][j] + EPS);
            const float d3 = fmaf(W1, H[2][j] + dn[j], H[3][j] + EPS);
            o[0][j] = __fdividef(tg[0][j], d0);
            o[3][j] = __fdividef(tg[3][j], d3);
        }
    };

    for (int it = 0; it < ITERS; ++it) {
        halfstep(v, b, u, 0);
        halfstep(u, a, v, 1);
    }

    // ---- cost over OWNED rows: u.(Mv); Mv = Hg(v) + W1*(T[r-1]+T[r+1]),
    //      T = v + 2*Hg(v) ----
    float HG[4][4], T[4][4];
#pragma unroll
    for (int i = 0; i < 4; ++i) {
        float lf = __shfl_up_sync(0xffffffffu, v[i][3], 1, 16);
        float rt = __shfl_down_sync(0xffffffffu, v[i][0], 1, 16);
        if (seg == 0)  lf = 0.f;
        if (seg == 15) rt = 0.f;
        HG[i][0] = W1 * (lf + v[i][1]);
        HG[i][1] = W1 * (v[i][0] + v[i][2]);
        HG[i][2] = W1 * (v[i][1] + v[i][3]);
        HG[i][3] = W1 * (v[i][2] + rt);
#pragma unroll
        for (int j = 0; j < 4; ++j) T[i][j] = fmaf(2.f, HG[i][j], v[i][j]);
    }
    // slot 0 reuse safe: its last readers finished before halfstep-99's barrier
    *(float4*)&HT[0][band + 1][c0] = make_float4(T[0][0], T[0][1], T[0][2], T[0][3]);
    *(float4*)&HB[0][band + 1][c0] = make_float4(T[3][0], T[3][1], T[3][2], T[3][3]);
    __syncthreads();
    const float4 u4 = *(const float4*)&HB[0][band][c0];
    const float4 d4 = *(const float4*)&HT[0][band + 2][c0];
    const float up[4] = {u4.x, u4.y, u4.z, u4.w};
    const float dn[4] = {d4.x, d4.y, d4.z, d4.w};

    float local = 0.f;
#pragma unroll
    for (int i = 0; i < 4; ++i) {
#pragma unroll
        for (int j = 0; j < 4; ++j) {
            const float tu = (i == 0) ? up[j] : T[i - 1][j];
            const float td = (i == 3) ? dn[j] : T[i + 1][j];
            const float mv = fmaf(W1, tu + td, HG[i][j]);
            local = fmaf(u[i][j], mv, local);
        }
    }
    local = own ? local : 0.f;

    // reduce over 2 warps
#pragma unroll
    for (int o = 16; o; o >>= 1) local += __shfl_xor_sync(0xffffffffu, local, o);
    if (l == 0) red[t >> 5] = local;
    __syncthreads();

    if (t == 0) {
        g_costs[blockIdx.x] = red[0] + red[1];
        __threadfence();
        const int prev = atomicAdd(&g_done, 1);
        if (prev == 8 * NBATCH - 1) {
            g_done = 0;
            __threadfence();
            float s = 0.f;
#pragma unroll 1
            for (int bb = 0; bb < NBATCH; ++bb) {
                float as = 0.f, bs = 0.f;
#pragma unroll
                for (int i = 0; i < 16; ++i) {
                    as += g_psum[0][bb][i];
                    bs += g_psum[1][bb][i];
                }
                float cst = 0.f;
#pragma unroll
                for (int k = 0; k < 8; ++k) cst += g_costs[8 * bb + k];
                s += ((as > 0.5f) && (bs > 0.5f)) ? cst : 0.f;
            }
            out[0] = s * (1.f / (float)NBATCH);
        }
    }
}

extern "C" void kernel_launch(void* const* d_in, const int* in_sizes, int n_in,
                              void* d_out, int out_size) {
    (void)in_sizes; (void)n_in; (void)out_size;
    const float* pred = (const float*)d_in[0];
    const float* gt   = (const float*)d_in[1];
    pool_kernel<<<512, 256>>>(pred, gt);
    sinkhorn_kernel<<<NBATCH * 8, 64>>>((float*)d_out);
}

// round 15
// speedup vs baseline: 1.3884x; 1.1606x over previous
#include <cuda_runtime.h>

// Sinkhorn OT loss on 64x64 pooled grids. K = exp(-C/0.1) is exact (to fp32)
// as two 3-tap separable passes, W1 = exp(-10).
// R15: R10's domain split (8 blocks/batch, 16-row window = 8 owned + 4+4
// halo), remapped so all three wins hold at once:
//   - CTA = 128 thr / 4 warps -> one warp per SMSP (R10's issue coverage)
//   - warp = one 4-row band, lane = 2 cols (float2) -> 8 cells/thread
//   - band rows 1,2 are INTERIOR: their whole V-phase (FMA+RCP+MUL) runs
//     BEFORE __syncthreads; post-BAR tail = 2 boundary rows only (R14's trick
//     without R14's half-idle SM).
// Horizontal stencil = distance-1 shuffles across the full warp.

#define NBATCH 16
#define ITERS  50
#define EPS    1e-8f
#define W1     4.5399929762484854e-05f   // exp(-10)

__device__ float g_pooled[2][NBATCH][4096];
__device__ float g_psum[2][NBATCH][16];    // per pool-block partial sums
__device__ float g_costs[NBATCH * 8];      // [batch*8 + block]
__device__ int   g_done;

// ---------------------------------------------------------------- pooling
__global__ __launch_bounds__(256) void pool_kernel(const float* __restrict__ pred,
                                                   const float* __restrict__ gt) {
    __shared__ float red[8];
    const int bid    = blockIdx.x;          // 0..511
    const int tensor = bid >> 8;
    const int batch  = (bid >> 4) & 15;
    const int rb     = bid & 15;            // block of 4 pooled rows
    const float* src = (tensor ? gt : pred) + (size_t)batch * 262144;

    const int pr = rb * 4 + (threadIdx.x >> 6);
    const int pc = threadIdx.x & 63;
    const float4* p = (const float4*)(src + (size_t)pr * 4096 + pc * 8);

    float s = 0.f;
#pragma unroll
    for (int y = 0; y < 8; ++y) {
        float4 v0 = p[y * 128];
        float4 v1 = p[y * 128 + 1];
        s += (v0.x + v0.y) + (v0.z + v0.w) + (v1.x + v1.y) + (v1.z + v1.w);
    }
    g_pooled[tensor][batch][pr * 64 + pc] = s;

    float v = s;
#pragma unroll
    for (int o = 16; o; o >>= 1) v += __shfl_xor_sync(0xffffffffu, v, o);
    const int w = threadIdx.x >> 5, l = threadIdx.x & 31;
    if (l == 0) red[w] = v;
    __syncthreads();
    if (threadIdx.x == 0) {
        float tot = ((red[0] + red[1]) + (red[2] + red[3]))
                  + ((red[4] + red[5]) + (red[6] + red[7]));
        g_psum[tensor][batch][rb] = tot;
    }
}

// ---------------------------------------------------------------- sinkhorn
__global__ __launch_bounds__(128, 1) void sinkhorn_kernel(float* __restrict__ out) {
    // seam rows, double-buffered by slot; index w+1; rows 0 & 5 = 0 pads
    __shared__ __align__(8) float HT[2][6][64];   // warp w's H row r0   (band top)
    __shared__ __align__(8) float HB[2][6][64];   // warp w's H row r0+3 (band bottom)
    __shared__ float red[4];

    const int t     = threadIdx.x;          // 0..127
    const int w     = t >> 5;               // warp = band 0..3 (4 rows each)
    const int l     = t & 31;
    const int c0    = 2 * l;                // lane's columns: c0, c0+1
    const int q     = blockIdx.x & 7;       // row-block within batch
    const int batch = blockIdx.x >> 3;
    const int r0    = 8 * q - 4 + 4 * w;    // window rows 8q-4 .. 8q+11
    const bool own  = (w == 1) || (w == 2); // owned rows 8q..8q+7

    // zero smem (incl. pad rows 0 and 5; stores only ever hit rows 1..4)
    for (int i = t; i < 2 * 6 * 64; i += 128) {
        ((float*)HT)[i] = 0.f;
        ((float*)HB)[i] = 0.f;
    }

    // ---- batch-wide sums from pool partials (fixed linear order) ----
    float asum = 0.f, bsum = 0.f;
#pragma unroll
    for (int i = 0; i < 16; ++i) {
        asum += g_psum[0][batch][i];
        bsum += g_psum[1][batch][i];
    }
    const float ra  = 1.f / fmaxf(asum, 1e-8f);
    const float rbv = 1.f / fmaxf(bsum, 1e-8f);

    // ---- load window rows (zero outside the 64-row grid) ----
    float2 a[4], b[4], u[4], v[4];
#pragma unroll
    for (int i = 0; i < 4; ++i) {
        const int r = r0 + i;
        if ((unsigned)r < 64u) {
            const float2 x = *(const float2*)&g_pooled[0][batch][r * 64 + c0];
            const float2 y = *(const float2*)&g_pooled[1][batch][r * 64 + c0];
            a[i] = make_float2(x.x * ra,  x.y * ra);
            b[i] = make_float2(y.x * rbv, y.y * rbv);
            u[i] = make_float2(1.f, 1.f);
        } else {
            a[i] = make_float2(0.f, 0.f);
            b[i] = make_float2(0.f, 0.f);
            u[i] = make_float2(0.f, 0.f);
        }
    }
    __syncthreads();   // pad init visible

    // out = tg / (Ve(He(in)) + eps). Interior rows 1,2 fully computed BEFORE
    // the barrier; only boundary rows 0,3 wait on the seam exchange.
    auto halfstep = [&](float2 (&o)[4], const float2 (&tg)[4],
                        const float2 (&in)[4], const int s) {
        float2 H[4];
#pragma unroll
        for (int i = 0; i < 4; ++i) {
            float lf = __shfl_up_sync(0xffffffffu, in[i].y, 1);    // col c0-1
            float rt = __shfl_down_sync(0xffffffffu, in[i].x, 1);  // col c0+2
            if (l == 0)  lf = 0.f;
            if (l == 31) rt = 0.f;
            H[i].x = fmaf(W1, lf + in[i].y, in[i].x);
            H[i].y = fmaf(W1, in[i].x + rt, in[i].y);
        }
        *(float2*)&HT[s][w + 1][c0] = H[0];
        *(float2*)&HB[s][w + 1][c0] = H[3];

        // interior rows 1,2: no seam dependence -> pre-BAR (fills the wait)
        {
            const float d1x = fmaf(W1, H[0].x + H[2].x, H[1].x + EPS);
            const float d1y = fmaf(W1, H[0].y + H[2].y, H[1].y + EPS);
            const float d2x = fmaf(W1, H[1].x + H[3].x, H[2].x + EPS);
            const float d2y = fmaf(W1, H[1].y + H[3].y, H[2].y + EPS);
            o[1].x = __fdividef(tg[1].x, d1x);
            o[1].y = __fdividef(tg[1].y, d1y);
            o[2].x = __fdividef(tg[2].x, d2x);
            o[2].y = __fdividef(tg[2].y, d2y);
        }
        __syncthreads();
        const float2 up = *(const float2*)&HB[s][w][c0];      // H row r0-1
        const float2 dn = *(const float2*)&HT[s][w + 2][c0];  // H row r0+4
        {
            const float d0x = fmaf(W1, up.x + H[1].x, H[0].x + EPS);
            const float d0y = fmaf(W1, up.y + H[1].y, H[0].y + EPS);
            const float d3x = fmaf(W1, H[2].x + dn.x, H[3].x + EPS);
            const float d3y = fmaf(W1, H[2].y + dn.y, H[3].y + EPS);
            o[0].x = __fdividef(tg[0].x, d0x);
            o[0].y = __fdividef(tg[0].y, d0y);
            o[3].x = __fdividef(tg[3].x, d3x);
            o[3].y = __fdividef(tg[3].y, d3y);
        }
    };

    for (int it = 0; it < ITERS; ++it) {
        halfstep(v, b, u, 0);
        halfstep(u, a, v, 1);
    }

    // ---- cost over OWNED rows: u.(Mv); Mv = Hg(v) + W1*(T[r-1]+T[r+1]),
    //      T = v + 2*Hg(v) ----
    float2 HG[4], T[4];
#pragma unroll
    for (int i = 0; i < 4; ++i) {
        float lf = __shfl_up_sync(0xffffffffu, v[i].y, 1);
        float rt = __shfl_down_sync(0xffffffffu, v[i].x, 1);
        if (l == 0)  lf = 0.f;
        if (l == 31) rt = 0.f;
        HG[i].x = W1 * (lf + v[i].y);
        HG[i].y = W1 * (v[i].x + rt);
        T[i].x  = fmaf(2.f, HG[i].x, v[i].x);
        T[i].y  = fmaf(2.f, HG[i].y, v[i].y);
    }
    // slot 0 reuse safe: its last readers finished before halfstep-99's barrier
    *(float2*)&HT[0][w + 1][c0] = T[0];
    *(float2*)&HB[0][w + 1][c0] = T[3];
    __syncthreads();
    const float2 up = *(const float2*)&HB[0][w][c0];
    const float2 dn = *(const float2*)&HT[0][w + 2][c0];

    float local = 0.f;
    {
        float mvx = fmaf(W1, up.x + T[1].x, HG[0].x);
        float mvy = fmaf(W1, up.y + T[1].y, HG[0].y);
        local = fmaf(u[0].x, mvx, fmaf(u[0].y, mvy, local));
        mvx = fmaf(W1, T[0].x + T[2].x, HG[1].x);
        mvy = fmaf(W1, T[0].y + T[2].y, HG[1].y);
        local = fmaf(u[1].x, mvx, fmaf(u[1].y, mvy, local));
        mvx = fmaf(W1, T[1].x + T[3].x, HG[2].x);
        mvy = fmaf(W1, T[1].y + T[3].y, HG[2].y);
        local = fmaf(u[2].x, mvx, fmaf(u[2].y, mvy, local));
        mvx = fmaf(W1, T[2].x + dn.x, HG[3].x);
        mvy = fmaf(W1, T[2].y + dn.y, HG[3].y);
        local = fmaf(u[3].x, mvx, fmaf(u[3].y, mvy, local));
    }
    local = own ? local : 0.f;

    // reduce over 4 warps
#pragma unroll
    for (int o = 16; o; o >>= 1) local += __shfl_xor_sync(0xffffffffu, local, o);
    if (l == 0) red[w] = local;
    __syncthreads();

    if (t == 0) {
        g_costs[blockIdx.x] = (red[0] + red[1]) + (red[2] + red[3]);
        __threadfence();
        const int prev = atomicAdd(&g_done, 1);
        if (prev == 8 * NBATCH - 1) {
            g_done = 0;
            __threadfence();
            float s = 0.f;
#pragma unroll 1
            for (int bb = 0; bb < NBATCH; ++bb) {
                float as = 0.f, bs = 0.f;
#pragma unroll
                for (int i = 0; i < 16; ++i) {
                    as += g_psum[0][bb][i];
                    bs += g_psum[1][bb][i];
                }
                float cst = 0.f;
#pragma unroll
                for (int k = 0; k < 8; ++k) cst += g_costs[8 * bb + k];
                s += ((as > 0.5f) && (bs > 0.5f)) ? cst : 0.f;
            }
            out[0] = s * (1.f / (float)NBATCH);
        }
    }
}

extern "C" void kernel_launch(void* const* d_in, const int* in_sizes, int n_in,
                              void* d_out, int out_size) {
    (void)in_sizes; (void)n_in; (void)out_size;
    const float* pred = (const float*)d_in[0];
    const float* gt   = (const float*)d_in[1];
    pool_kernel<<<512, 256>>>(pred, gt);
    sinkhorn_kernel<<<NBATCH * 8, 128>>>((float*)d_out);
}